// round 13
// baseline (speedup 1.0000x reference)
#include <cuda_runtime.h>
#include <cstdint>

// Problem constants
#define T_STEPS 512
#define BATCH   64
#define N_IN    512
#define HID     1024

// LSNN parameters
#define DT_TAU_MEM   0.1f
#define DT_TAU_SYN   0.2f
#define DT_TAU_ADAPT 1.25e-6f
#define VTH          1.0f
#define BETA         1.8f

// Fused-kernel geometry
#define N_SCAN_CTAS  32                             // 2 batches per scan CTA
#define N_GEMM_CTAS  264
#define N_TOTAL_CTAS (N_SCAN_CTAS + N_GEMM_CTAS)   // 296 = 148 SMs * 2
#define N_ROWBLK     256                            // (T*B)/128 row-blocks
#define N_COLBLK     8                              // HID/128
#define N_TILES      (N_ROWBLK * N_COLBLK)          // 2048

// ---------------------------------------------------------------------------
// Scratch
// ---------------------------------------------------------------------------
__device__ float g_curin[(size_t)T_STEPS * BATCH * HID];   // x @ w_in^T, [T,B,H]
__device__ float g_wrecT[(size_t)HID * HID];               // w_rec^T
__device__ float g_winT [(size_t)N_IN * HID];              // w_in^T
__device__ int   g_cnt[N_ROWBLK];                          // col-tiles done per row-block
__device__ int   g_tile;                                   // dynamic tile queue head

// ---------------------------------------------------------------------------
// Packed fp32x2 helpers
// ---------------------------------------------------------------------------
__device__ __forceinline__ unsigned long long pack_f32x2(float lo, float hi)
{
    unsigned long long r;
    asm("mov.b64 %0, {%1, %2};" : "=l"(r) : "r"(__float_as_uint(lo)), "r"(__float_as_uint(hi)));
    return r;
}
__device__ __forceinline__ void fma_f32x2(unsigned long long& d,
                                          unsigned long long a, unsigned long long b)
{
    asm("fma.rn.f32x2 %0, %1, %2, %0;" : "+l"(d) : "l"(a), "l"(b));
}
__device__ __forceinline__ void add_f32x2(unsigned long long& d, unsigned long long a)
{
    asm("add.rn.f32x2 %0, %0, %1;" : "+l"(d) : "l"(a));
}
__device__ __forceinline__ float2 unpack_f32x2(unsigned long long p)
{
    unsigned int lo, hi;
    asm("mov.b64 {%0, %1}, %2;" : "=r"(lo), "=r"(hi) : "l"(p));
    return make_float2(__uint_as_float(lo), __uint_as_float(hi));
}

// ---------------------------------------------------------------------------
// Tiled transposes
// ---------------------------------------------------------------------------
__device__ __forceinline__ void transpose_impl(const float* __restrict__ in,
                                               float* __restrict__ out,
                                               int rows, int cols)
{
    __shared__ float tile[32][33];
    int c = blockIdx.x * 32 + threadIdx.x;
    int r = blockIdx.y * 32 + threadIdx.y;
#pragma unroll
    for (int j = 0; j < 32; j += 8) {
        if (r + j < rows && c < cols)
            tile[threadIdx.y + j][threadIdx.x] = in[(size_t)(r + j) * cols + c];
    }
    __syncthreads();
    int c2 = blockIdx.y * 32 + threadIdx.x;
    int r2 = blockIdx.x * 32 + threadIdx.y;
#pragma unroll
    for (int j = 0; j < 32; j += 8) {
        if (r2 + j < cols && c2 < rows)
            out[(size_t)(r2 + j) * rows + c2] = tile[threadIdx.x][threadIdx.y + j];
    }
}

__global__ void transpose_wrec_kernel(const float* __restrict__ w_rec)
{
    transpose_impl(w_rec, g_wrecT, HID, HID);
}

__global__ void transpose_win_kernel(const float* __restrict__ w_in)
{
    transpose_impl(w_in, g_winT, HID, N_IN);
}

__global__ void init_flags_kernel()
{
    if (threadIdx.x < N_ROWBLK) g_cnt[threadIdx.x] = 0;
    if (threadIdx.x == 0) g_tile = 0;
}

// ---------------------------------------------------------------------------
// Fused kernel: 296 CTAs of 256 threads.
//   bid <  32 : LSNN scan, TWO batches per CTA (half-CTA per batch)
//   bid >= 32 : GEMM worker pulling tiles from a dynamic t-ordered queue
// ---------------------------------------------------------------------------
#define BM 128
#define BN 128
#define BK 8
#define TM 8
#define TN 8
#define SMEM_BYTES 16896

__device__ __forceinline__ void gemm_role(unsigned char* s_raw,
                                          const float* __restrict__ A)
{
    float (*As)[BK][BM] = reinterpret_cast<float (*)[BK][BM]>(s_raw);
    float (*Bs)[BK][BN] = reinterpret_cast<float (*)[BK][BN]>(s_raw + 8192);
    int* s_tile = reinterpret_cast<int*>(s_raw + 16384);

    const int K = N_IN;
    const int N = HID;
    const int tid = threadIdx.x;

    const int arow = tid >> 1;
    const int ak   = (tid & 1) * 4;
    const int brow = tid >> 5;
    const int bcol = (tid & 31) * 4;
    const int tx = (tid & 15) * TN;
    const int ty = (tid >> 4) * TM;

    for (;;) {
        if (tid == 0) *s_tile = atomicAdd(&g_tile, 1);
        __syncthreads();
        const int tile = *s_tile;
        __syncthreads();
        if (tile >= N_TILES) break;

        const int rb = tile >> 3;       // row-block (covers t = 2*rb, 2*rb+1)
        const int cb = tile & 7;
        const int bm = rb * BM;
        const int bn = cb * BN;

        unsigned long long acc2[TM][TN / 2];
#pragma unroll
        for (int m = 0; m < TM; m++)
#pragma unroll
            for (int j = 0; j < TN / 2; j++) acc2[m][j] = 0ull;

        const float* Aptr = A + (size_t)(bm + arow) * K + ak;
        const float* Bptr = g_winT + (size_t)brow * N + bn + bcol;

        float4 av = *(const float4*)Aptr;  Aptr += BK;
        float4 bv = *(const float4*)Bptr;  Bptr += (size_t)BK * N;
        As[0][ak + 0][arow] = av.x;
        As[0][ak + 1][arow] = av.y;
        As[0][ak + 2][arow] = av.z;
        As[0][ak + 3][arow] = av.w;
        *(float4*)&Bs[0][brow][bcol] = bv;
        __syncthreads();

        const int NIT = K / BK;   // 64
        for (int k0 = 0; k0 < NIT; k0++) {
            const int cur = k0 & 1;

            if (k0 + 1 < NIT) {
                av = *(const float4*)Aptr;  Aptr += BK;
                bv = *(const float4*)Bptr;  Bptr += (size_t)BK * N;
            }

#pragma unroll
            for (int kk = 0; kk < BK; kk++) {
                const float4* asp = (const float4*)&As[cur][kk][ty];
                float4 a0 = asp[0];
                float4 a1 = asp[1];
                unsigned long long a2[TM];
                a2[0] = pack_f32x2(a0.x, a0.x);
                a2[1] = pack_f32x2(a0.y, a0.y);
                a2[2] = pack_f32x2(a0.z, a0.z);
                a2[3] = pack_f32x2(a0.w, a0.w);
                a2[4] = pack_f32x2(a1.x, a1.x);
                a2[5] = pack_f32x2(a1.y, a1.y);
                a2[6] = pack_f32x2(a1.z, a1.z);
                a2[7] = pack_f32x2(a1.w, a1.w);

                const ulonglong2* bsp = (const ulonglong2*)&Bs[cur][kk][tx];
                ulonglong2 bq0 = bsp[0];
                ulonglong2 bq1 = bsp[1];
                unsigned long long bb[TN / 2] = {bq0.x, bq0.y, bq1.x, bq1.y};

#pragma unroll
                for (int m = 0; m < TM; m++)
#pragma unroll
                    for (int j = 0; j < TN / 2; j++)
                        fma_f32x2(acc2[m][j], a2[m], bb[j]);
            }

            if (k0 + 1 < NIT) {
                const int nxt = cur ^ 1;
                As[nxt][ak + 0][arow] = av.x;
                As[nxt][ak + 1][arow] = av.y;
                As[nxt][ak + 2][arow] = av.z;
                As[nxt][ak + 3][arow] = av.w;
                *(float4*)&Bs[nxt][brow][bcol] = bv;
                __syncthreads();
            }
        }

        float* Cbase = g_curin + (size_t)(bm + ty) * N + bn + tx;
#pragma unroll
        for (int m = 0; m < TM; m++) {
            float* crow = Cbase + (size_t)m * N;
#pragma unroll
            for (int j = 0; j < TN / 2; j += 2) {
                float2 v0 = unpack_f32x2(acc2[m][j]);
                float2 v1 = unpack_f32x2(acc2[m][j + 1]);
                *(float4*)(crow + 2 * j) = make_float4(v0.x, v0.y, v1.x, v1.y);
            }
        }

        __syncthreads();
        if (tid == 0) {
            __threadfence();
            atomicAdd(&g_cnt[rb], 1);
        }
        __syncthreads();
    }
}

// Scan: warps 0-3 -> batch 2*bid, warps 4-7 -> batch 2*bid+1.
// 8 consecutive neurons per thread. Spike list in shorts, per half-CTA.
// Compaction via popc only (no shuffles).
__device__ __forceinline__ void scan_role(unsigned char* s_raw,
                                          float* __restrict__ out)
{
    short (*s_list)[2][HID] = reinterpret_cast<short (*)[2][HID]>(s_raw); // [half][buf][..] 8KB
    int*  s_wc              = reinterpret_cast<int*>(s_raw + 8192);       // [half*4 + w]

    const int tid   = threadIdx.x;
    const int half  = tid >> 7;          // 0 or 1
    const int htid  = tid & 127;
    const int lane  = tid & 31;
    const int wid4  = (tid >> 5) & 3;    // warp within half
    const int h0    = htid * 8;
    const int batch = 2 * blockIdx.x + half;
    const unsigned FULL = 0xffffffffu;

    float v[8], cur[8], bth[8], zl[8];
#pragma unroll
    for (int j = 0; j < 8; j++) { v[j] = 0.f; cur[j] = 0.f; bth[j] = VTH; zl[j] = 0.f; }
    int cnt = 0;
    int buf = 0;

    const float* cin  = g_curin + (size_t)batch * HID + h0;
    float*       outp = out     + (size_t)batch * HID + h0;
    const size_t strideT = (size_t)BATCH * HID;

    float4 gin0, gin1, pg0, pg1;

    for (int t = 0; t < T_STEPS; t++) {
        if ((t & 1) == 0) {
            if (tid == 0) {
                int* flag = &g_cnt[t >> 1];
                int c;
                for (;;) {
                    asm volatile("ld.acquire.gpu.global.b32 %0, [%1];"
                                 : "=r"(c) : "l"(flag) : "memory");
                    if (c >= N_COLBLK) break;
                    __nanosleep(256);
                }
            }
            __syncthreads();
            __threadfence();
            const float* p = cin + (size_t)t * strideT;
            gin0 = *(const float4*)p;
            gin1 = *(const float4*)(p + 4);
            pg0  = *(const float4*)(p + strideT);
            pg1  = *(const float4*)(p + strideT + 4);
        } else {
            gin0 = pg0; gin1 = pg1;
        }

        // ---- recurrent gather (ascending spike order, packed adds) ----
        unsigned long long r01 = 0ull, r23 = 0ull, r45 = 0ull, r67 = 0ull;
        {
            const short* lst = s_list[half][buf];
            int k = 0;
            for (; k + 2 <= cnt; k += 2) {
                int i0 = lst[k], i1 = lst[k + 1];
                const ulonglong2* p0 = (const ulonglong2*)(g_wrecT + (size_t)i0 * HID + h0);
                const ulonglong2* p1 = (const ulonglong2*)(g_wrecT + (size_t)i1 * HID + h0);
                ulonglong2 w0a = p0[0], w0b = p0[1];
                ulonglong2 w1a = p1[0], w1b = p1[1];
                add_f32x2(r01, w0a.x); add_f32x2(r23, w0a.y);
                add_f32x2(r45, w0b.x); add_f32x2(r67, w0b.y);
                add_f32x2(r01, w1a.x); add_f32x2(r23, w1a.y);
                add_f32x2(r45, w1b.x); add_f32x2(r67, w1b.y);
            }
            if (k < cnt) {
                int i0 = lst[k];
                const ulonglong2* p0 = (const ulonglong2*)(g_wrecT + (size_t)i0 * HID + h0);
                ulonglong2 w0a = p0[0], w0b = p0[1];
                add_f32x2(r01, w0a.x); add_f32x2(r23, w0a.y);
                add_f32x2(r45, w0b.x); add_f32x2(r67, w0b.y);
            }
        }
        float rec[8];
        {
            float2 a = unpack_f32x2(r01); rec[0] = a.x; rec[1] = a.y;
            float2 b = unpack_f32x2(r23); rec[2] = b.x; rec[3] = b.y;
            float2 c = unpack_f32x2(r45); rec[4] = c.x; rec[5] = c.y;
            float2 d = unpack_f32x2(r67); rec[6] = d.x; rec[7] = d.y;
        }
        const float ginv[8] = {gin0.x, gin0.y, gin0.z, gin0.w,
                               gin1.x, gin1.y, gin1.z, gin1.w};

        // ---- elementwise dynamics (same expression order as reference) ----
        bool z[8];
        float zf[8];
#pragma unroll
        for (int j = 0; j < 8; j++) {
            float vd   = v[j] + DT_TAU_MEM * (cur[j] - v[j]);
            float idec = cur[j] - DT_TAU_SYN * cur[j];
            float bd   = bth[j] + DT_TAU_ADAPT * (VTH - bth[j]);
            z[j]  = (vd - bd) > 0.0f;
            zf[j] = z[j] ? 1.0f : 0.0f;
            v[j]   = z[j] ? 0.0f : vd;
            bth[j] = bd + (z[j] ? BETA : 0.0f);
            cur[j] = (idec + ginv[j]) + rec[j];
            zl[j]  = zf[j];
        }

        float* op = outp + (size_t)t * strideT;
        *(float4*)op       = make_float4(zf[0], zf[1], zf[2], zf[3]);
        *(float4*)(op + 4) = make_float4(zf[4], zf[5], zf[6], zf[7]);

        // ---- compaction: popc positions only, no shuffles ----
        unsigned b0 = __ballot_sync(FULL, z[0]);
        unsigned b1 = __ballot_sync(FULL, z[1]);
        unsigned b2 = __ballot_sync(FULL, z[2]);
        unsigned b3 = __ballot_sync(FULL, z[3]);
        unsigned b4 = __ballot_sync(FULL, z[4]);
        unsigned b5 = __ballot_sync(FULL, z[5]);
        unsigned b6 = __ballot_sync(FULL, z[6]);
        unsigned b7 = __ballot_sync(FULL, z[7]);
        const unsigned lt = (1u << lane) - 1u;
        int tex  = __popc(b0 & lt) + __popc(b1 & lt) + __popc(b2 & lt) + __popc(b3 & lt)
                 + __popc(b4 & lt) + __popc(b5 & lt) + __popc(b6 & lt) + __popc(b7 & lt);
        int wtot = __popc(b0) + __popc(b1) + __popc(b2) + __popc(b3)
                 + __popc(b4) + __popc(b5) + __popc(b6) + __popc(b7);

        if (lane == 0) s_wc[half * 4 + wid4] = wtot;
        __syncthreads();   // (X) counts visible; old-list reads complete

        int c0 = s_wc[half * 4 + 0];
        int c1 = s_wc[half * 4 + 1];
        int c2 = s_wc[half * 4 + 2];
        int c3 = s_wc[half * 4 + 3];
        int total = c0 + c1 + c2 + c3;
        int base = (wid4 > 0 ? c0 : 0) + (wid4 > 1 ? c1 : 0) + (wid4 > 2 ? c2 : 0);

        const int nbuf = buf ^ 1;
        short* nl = s_list[half][nbuf];
        int p = base + tex;
        if (z[0]) nl[p++] = (short)(h0 + 0);
        if (z[1]) nl[p++] = (short)(h0 + 1);
        if (z[2]) nl[p++] = (short)(h0 + 2);
        if (z[3]) nl[p++] = (short)(h0 + 3);
        if (z[4]) nl[p++] = (short)(h0 + 4);
        if (z[5]) nl[p++] = (short)(h0 + 5);
        if (z[6]) nl[p++] = (short)(h0 + 6);
        if (z[7]) nl[p]   = (short)(h0 + 7);

        cnt = total;
        buf = nbuf;
        __syncthreads();   // (Y) new list ready
    }

    // final states: (zf, vf, if, bf) appended after outs [T,B,H]
    const size_t BH = (size_t)BATCH * HID;
    float* fbase = out + (size_t)T_STEPS * BH + (size_t)batch * HID + h0;
    *(float4*)(fbase + 0 * BH)     = make_float4(zl[0], zl[1], zl[2], zl[3]);
    *(float4*)(fbase + 0 * BH + 4) = make_float4(zl[4], zl[5], zl[6], zl[7]);
    *(float4*)(fbase + 1 * BH)     = make_float4(v[0], v[1], v[2], v[3]);
    *(float4*)(fbase + 1 * BH + 4) = make_float4(v[4], v[5], v[6], v[7]);
    *(float4*)(fbase + 2 * BH)     = make_float4(cur[0], cur[1], cur[2], cur[3]);
    *(float4*)(fbase + 2 * BH + 4) = make_float4(cur[4], cur[5], cur[6], cur[7]);
    *(float4*)(fbase + 3 * BH)     = make_float4(bth[0], bth[1], bth[2], bth[3]);
    *(float4*)(fbase + 3 * BH + 4) = make_float4(bth[4], bth[5], bth[6], bth[7]);
}

__global__ void __launch_bounds__(256, 2)
fused_kernel(const float* __restrict__ A, float* __restrict__ out)
{
    __shared__ __align__(16) unsigned char s_raw[SMEM_BYTES];
    if (blockIdx.x < N_SCAN_CTAS) scan_role(s_raw, out);
    else                          gemm_role(s_raw, A);
}

// ---------------------------------------------------------------------------
// Launch
// ---------------------------------------------------------------------------
extern "C" void kernel_launch(void* const* d_in, const int* in_sizes, int n_in,
                              void* d_out, int out_size)
{
    const float* x     = (const float*)d_in[0];  // [T, B, N_IN]
    const float* w_in  = (const float*)d_in[1];  // [H, N_IN]
    const float* w_rec = (const float*)d_in[2];  // [H, H]
    float* out = (float*)d_out;

    {
        dim3 blk(32, 8);
        dim3 g2(N_IN / 32, HID / 32);
        transpose_win_kernel<<<g2, blk>>>(w_in);
        dim3 g1(HID / 32, HID / 32);
        transpose_wrec_kernel<<<g1, blk>>>(w_rec);
    }

    init_flags_kernel<<<1, 256>>>();

    fused_kernel<<<N_TOTAL_CTAS, 256>>>(x, out);
}

// round 15
// speedup vs baseline: 1.0582x; 1.0582x over previous
#include <cuda_runtime.h>
#include <cstdint>

// Problem constants
#define T_STEPS 512
#define BATCH   64
#define N_IN    512
#define HID     1024

// LSNN parameters
#define DT_TAU_MEM   0.1f
#define DT_TAU_SYN   0.2f
#define DT_TAU_ADAPT 1.25e-6f
#define VTH          1.0f
#define BETA         1.8f

// Fused-kernel geometry.
// Classic placement maps bid and bid+148 to the SAME SM. Scan CTAs are
// bids {0..31} u {148..179}: 2 scan CTAs on each of 32 SMs. The remaining
// 116 SMs carry 2 GEMM CTAs each (fully saturated).
#define N_TOTAL_CTAS 296                            // 148 SMs * 2
#define N_ROWBLK     256                            // (T*B)/128 row-blocks
#define N_COLBLK     8                              // HID/128
#define N_TILES      (N_ROWBLK * N_COLBLK)          // 2048

// ---------------------------------------------------------------------------
// Scratch
// ---------------------------------------------------------------------------
__device__ float g_curin[(size_t)T_STEPS * BATCH * HID];   // x @ w_in^T, [T,B,H]
__device__ float g_wrecT[(size_t)HID * HID];               // w_rec^T
__device__ float g_winT [(size_t)N_IN * HID];              // w_in^T
__device__ int   g_cnt[N_ROWBLK];                          // col-tiles done per row-block
__device__ int   g_tile;                                   // dynamic tile queue head

// ---------------------------------------------------------------------------
// Packed fp32x2 helpers
// ---------------------------------------------------------------------------
__device__ __forceinline__ unsigned long long pack_f32x2(float lo, float hi)
{
    unsigned long long r;
    asm("mov.b64 %0, {%1, %2};" : "=l"(r) : "r"(__float_as_uint(lo)), "r"(__float_as_uint(hi)));
    return r;
}
__device__ __forceinline__ void fma_f32x2(unsigned long long& d,
                                          unsigned long long a, unsigned long long b)
{
    asm("fma.rn.f32x2 %0, %1, %2, %0;" : "+l"(d) : "l"(a), "l"(b));
}
__device__ __forceinline__ void add_f32x2(unsigned long long& d, unsigned long long a)
{
    asm("add.rn.f32x2 %0, %0, %1;" : "+l"(d) : "l"(a));
}
__device__ __forceinline__ float2 unpack_f32x2(unsigned long long p)
{
    unsigned int lo, hi;
    asm("mov.b64 {%0, %1}, %2;" : "=r"(lo), "=r"(hi) : "l"(p));
    return make_float2(__uint_as_float(lo), __uint_as_float(hi));
}

// ---------------------------------------------------------------------------
// Tiled transposes
// ---------------------------------------------------------------------------
__device__ __forceinline__ void transpose_impl(const float* __restrict__ in,
                                               float* __restrict__ out,
                                               int rows, int cols)
{
    __shared__ float tile[32][33];
    int c = blockIdx.x * 32 + threadIdx.x;
    int r = blockIdx.y * 32 + threadIdx.y;
#pragma unroll
    for (int j = 0; j < 32; j += 8) {
        if (r + j < rows && c < cols)
            tile[threadIdx.y + j][threadIdx.x] = in[(size_t)(r + j) * cols + c];
    }
    __syncthreads();
    int c2 = blockIdx.y * 32 + threadIdx.x;
    int r2 = blockIdx.x * 32 + threadIdx.y;
#pragma unroll
    for (int j = 0; j < 32; j += 8) {
        if (r2 + j < cols && c2 < rows)
            out[(size_t)(r2 + j) * rows + c2] = tile[threadIdx.x][threadIdx.y + j];
    }
}

__global__ void transpose_wrec_kernel(const float* __restrict__ w_rec)
{
    transpose_impl(w_rec, g_wrecT, HID, HID);
}

__global__ void transpose_win_kernel(const float* __restrict__ w_in)
{
    transpose_impl(w_in, g_winT, HID, N_IN);
}

__global__ void init_flags_kernel()
{
    if (threadIdx.x < N_ROWBLK) g_cnt[threadIdx.x] = 0;
    if (threadIdx.x == 0) g_tile = 0;
}

// ---------------------------------------------------------------------------
// Fused kernel roles
// ---------------------------------------------------------------------------
#define BM 128
#define BN 128
#define BK 8
#define TM 8
#define TN 8
#define SMEM_BYTES 16896

__device__ __forceinline__ void gemm_role(unsigned char* s_raw,
                                          const float* __restrict__ A)
{
    float (*As)[BK][BM] = reinterpret_cast<float (*)[BK][BM]>(s_raw);
    float (*Bs)[BK][BN] = reinterpret_cast<float (*)[BK][BN]>(s_raw + 8192);
    int* s_tile = reinterpret_cast<int*>(s_raw + 16384);

    const int K = N_IN;
    const int N = HID;
    const int tid = threadIdx.x;

    const int arow = tid >> 1;
    const int ak   = (tid & 1) * 4;
    const int brow = tid >> 5;
    const int bcol = (tid & 31) * 4;
    const int tx = (tid & 15) * TN;
    const int ty = (tid >> 4) * TM;

    for (;;) {
        // grab next tile in t-major order; single barrier (end-of-tile
        // barrier orders the next overwrite of s_tile)
        if (tid == 0) *s_tile = atomicAdd(&g_tile, 1);
        __syncthreads();
        const int tile = *s_tile;
        if (tile >= N_TILES) break;

        const int rb = tile >> 3;       // row-block (covers t = 2*rb, 2*rb+1)
        const int cb = tile & 7;
        const int bm = rb * BM;
        const int bn = cb * BN;

        unsigned long long acc2[TM][TN / 2];
#pragma unroll
        for (int m = 0; m < TM; m++)
#pragma unroll
            for (int j = 0; j < TN / 2; j++) acc2[m][j] = 0ull;

        const float* Aptr = A + (size_t)(bm + arow) * K + ak;
        const float* Bptr = g_winT + (size_t)brow * N + bn + bcol;

        float4 av = *(const float4*)Aptr;  Aptr += BK;
        float4 bv = *(const float4*)Bptr;  Bptr += (size_t)BK * N;
        As[0][ak + 0][arow] = av.x;
        As[0][ak + 1][arow] = av.y;
        As[0][ak + 2][arow] = av.z;
        As[0][ak + 3][arow] = av.w;
        *(float4*)&Bs[0][brow][bcol] = bv;
        __syncthreads();

        const int NIT = K / BK;   // 64
        for (int k0 = 0; k0 < NIT; k0++) {
            const int cur = k0 & 1;

            if (k0 + 1 < NIT) {
                av = *(const float4*)Aptr;  Aptr += BK;
                bv = *(const float4*)Bptr;  Bptr += (size_t)BK * N;
            }

#pragma unroll
            for (int kk = 0; kk < BK; kk++) {
                const float4* asp = (const float4*)&As[cur][kk][ty];
                float4 a0 = asp[0];
                float4 a1 = asp[1];
                unsigned long long a2[TM];
                a2[0] = pack_f32x2(a0.x, a0.x);
                a2[1] = pack_f32x2(a0.y, a0.y);
                a2[2] = pack_f32x2(a0.z, a0.z);
                a2[3] = pack_f32x2(a0.w, a0.w);
                a2[4] = pack_f32x2(a1.x, a1.x);
                a2[5] = pack_f32x2(a1.y, a1.y);
                a2[6] = pack_f32x2(a1.z, a1.z);
                a2[7] = pack_f32x2(a1.w, a1.w);

                const ulonglong2* bsp = (const ulonglong2*)&Bs[cur][kk][tx];
                ulonglong2 bq0 = bsp[0];
                ulonglong2 bq1 = bsp[1];
                unsigned long long bb[TN / 2] = {bq0.x, bq0.y, bq1.x, bq1.y};

#pragma unroll
                for (int m = 0; m < TM; m++)
#pragma unroll
                    for (int j = 0; j < TN / 2; j++)
                        fma_f32x2(acc2[m][j], a2[m], bb[j]);
            }

            if (k0 + 1 < NIT) {
                const int nxt = cur ^ 1;
                As[nxt][ak + 0][arow] = av.x;
                As[nxt][ak + 1][arow] = av.y;
                As[nxt][ak + 2][arow] = av.z;
                As[nxt][ak + 3][arow] = av.w;
                *(float4*)&Bs[nxt][brow][bcol] = bv;
                __syncthreads();
            }
        }

        float* Cbase = g_curin + (size_t)(bm + ty) * N + bn + tx;
#pragma unroll
        for (int m = 0; m < TM; m++) {
            float* crow = Cbase + (size_t)m * N;
#pragma unroll
            for (int j = 0; j < TN / 2; j += 2) {
                float2 v0 = unpack_f32x2(acc2[m][j]);
                float2 v1 = unpack_f32x2(acc2[m][j + 1]);
                *(float4*)(crow + 2 * j) = make_float4(v0.x, v0.y, v1.x, v1.y);
            }
        }

        __syncthreads();                  // all threads' stores issued
        if (tid == 0) {
            __threadfence();              // make them device-visible
            atomicAdd(&g_cnt[rb], 1);     // publish this col-tile
        }
        __syncthreads();                  // smem reuse + s_tile overwrite safe
    }
}

// Scan (r12 structure): one CTA per batch, 256 threads, 4 neurons/thread.
__device__ __forceinline__ void scan_role(unsigned char* s_raw,
                                          float* __restrict__ out,
                                          int batch)
{
    int  (*s_list)[HID] = reinterpret_cast<int (*)[HID]>(s_raw);       // 2 x 1024 ints
    int*  s_warpcnt     = reinterpret_cast<int*>(s_raw + 8192);        // 8 ints

    const int tid   = threadIdx.x;
    const int lane  = tid & 31;
    const int wid   = tid >> 5;
    const int h0    = tid * 4;
    const unsigned FULL = 0xffffffffu;

    float v[4]   = {0.f, 0.f, 0.f, 0.f};
    float cur[4] = {0.f, 0.f, 0.f, 0.f};
    float bth[4] = {VTH, VTH, VTH, VTH};
    float zl[4]  = {0.f, 0.f, 0.f, 0.f};
    int cnt = 0;
    int buf = 0;

    const float* cin  = g_curin + (size_t)batch * HID + h0;
    float*       outp = out     + (size_t)batch * HID + h0;
    const size_t strideT = (size_t)BATCH * HID;

    float4 gin, pgin;

    for (int t = 0; t < T_STEPS; t++) {
        if ((t & 1) == 0) {
            // wait for row-block t/2 (covers steps t and t+1, all batches)
            if (tid == 0) {
                int* flag = &g_cnt[t >> 1];
                int c;
                for (;;) {
                    asm volatile("ld.acquire.gpu.global.b32 %0, [%1];"
                                 : "=r"(c) : "l"(flag) : "memory");
                    if (c >= N_COLBLK) break;
                    __nanosleep(256);
                }
            }
            __syncthreads();
            __threadfence();   // order subsequent data loads after the flag read
            gin  = *(const float4*)(cin + (size_t)t * strideT);
            pgin = *(const float4*)(cin + (size_t)(t + 1) * strideT);
        } else {
            gin = pgin;
        }

        // recurrent input: sum of w_recT rows over previous step's spikes
        unsigned long long r01 = 0ull, r23 = 0ull;
        {
            const int* lst = s_list[buf];
            const int4* lst4 = (const int4*)lst;
            int k = 0;
            for (; k + 4 <= cnt; k += 4) {
                int4 i4 = lst4[k >> 2];
                ulonglong2 w0 = *(const ulonglong2*)(g_wrecT + (size_t)i4.x * HID + h0);
                ulonglong2 w1 = *(const ulonglong2*)(g_wrecT + (size_t)i4.y * HID + h0);
                ulonglong2 w2 = *(const ulonglong2*)(g_wrecT + (size_t)i4.z * HID + h0);
                ulonglong2 w3 = *(const ulonglong2*)(g_wrecT + (size_t)i4.w * HID + h0);
                add_f32x2(r01, w0.x); add_f32x2(r23, w0.y);
                add_f32x2(r01, w1.x); add_f32x2(r23, w1.y);
                add_f32x2(r01, w2.x); add_f32x2(r23, w2.y);
                add_f32x2(r01, w3.x); add_f32x2(r23, w3.y);
            }
            for (; k < cnt; k++) {
                ulonglong2 w = *(const ulonglong2*)(g_wrecT + (size_t)lst[k] * HID + h0);
                add_f32x2(r01, w.x); add_f32x2(r23, w.y);
            }
        }
        float rec[4];
        {
            float2 a = unpack_f32x2(r01);
            float2 b = unpack_f32x2(r23);
            rec[0] = a.x; rec[1] = a.y; rec[2] = b.x; rec[3] = b.y;
        }
        const float ginv[4] = {gin.x, gin.y, gin.z, gin.w};

        // elementwise dynamics
        bool z[4];
        float zf[4];
#pragma unroll
        for (int j = 0; j < 4; j++) {
            float vd   = v[j] + DT_TAU_MEM * (cur[j] - v[j]);
            float idec = cur[j] - DT_TAU_SYN * cur[j];
            float bd   = bth[j] + DT_TAU_ADAPT * (VTH - bth[j]);
            z[j]  = (vd - bd) > 0.0f;
            zf[j] = z[j] ? 1.0f : 0.0f;
            v[j]   = z[j] ? 0.0f : vd;
            bth[j] = bd + (z[j] ? BETA : 0.0f);
            cur[j] = (idec + ginv[j]) + rec[j];
            zl[j]  = zf[j];
        }

        *(float4*)(outp + (size_t)t * strideT) = make_float4(zf[0], zf[1], zf[2], zf[3]);

        // rebuild spike list (double-buffered, 2 barriers)
        int mycnt = (int)z[0] + (int)z[1] + (int)z[2] + (int)z[3];

        int inc = mycnt;
#pragma unroll
        for (int off = 1; off < 32; off *= 2) {
            int nbr = __shfl_up_sync(FULL, inc, off);
            if (lane >= off) inc += nbr;
        }
        int tex = inc - mycnt;
        if (lane == 31) s_warpcnt[wid] = inc;
        __syncthreads();

        int wc = (lane < 8) ? s_warpcnt[lane] : 0;
        int winc = wc;
#pragma unroll
        for (int off = 1; off < 8; off *= 2) {
            int nbr = __shfl_up_sync(FULL, winc, off);
            if (lane >= off) winc += nbr;
        }
        int total = __shfl_sync(FULL, winc, 7);
        int wbase = __shfl_sync(FULL, winc, wid) - __shfl_sync(FULL, wc, wid);

        const int nbuf = buf ^ 1;
        int p = wbase + tex;
        int* nl = s_list[nbuf];
        if (z[0]) nl[p++] = h0 + 0;
        if (z[1]) nl[p++] = h0 + 1;
        if (z[2]) nl[p++] = h0 + 2;
        if (z[3]) nl[p++] = h0 + 3;

        cnt = total;
        buf = nbuf;
        __syncthreads();
    }

    // final states: (zf, vf, if, bf) appended after outs [T,B,H]
    const size_t BH = (size_t)BATCH * HID;
    float* fbase = out + (size_t)T_STEPS * BH + (size_t)batch * HID + h0;
    *(float4*)(fbase + 0 * BH) = make_float4(zl[0], zl[1], zl[2], zl[3]);
    *(float4*)(fbase + 1 * BH) = make_float4(v[0], v[1], v[2], v[3]);
    *(float4*)(fbase + 2 * BH) = make_float4(cur[0], cur[1], cur[2], cur[3]);
    *(float4*)(fbase + 3 * BH) = make_float4(bth[0], bth[1], bth[2], bth[3]);
}

__global__ void __launch_bounds__(256, 2)
fused_kernel(const float* __restrict__ A, float* __restrict__ out)
{
    __shared__ __align__(16) unsigned char s_raw[SMEM_BYTES];
    const int bid = blockIdx.x;
    // Scan CTAs paired on 32 SMs: bids {0..31} and {148..179} share SMs
    // under classic placement (bid and bid+148 -> same SM).
    if (bid < 32)                       scan_role(s_raw, out, bid);
    else if (bid >= 148 && bid < 180)   scan_role(s_raw, out, bid - 116);  // 32..63
    else                                gemm_role(s_raw, A);
}

// ---------------------------------------------------------------------------
// Launch
// ---------------------------------------------------------------------------
extern "C" void kernel_launch(void* const* d_in, const int* in_sizes, int n_in,
                              void* d_out, int out_size)
{
    const float* x     = (const float*)d_in[0];  // [T, B, N_IN]
    const float* w_in  = (const float*)d_in[1];  // [H, N_IN]
    const float* w_rec = (const float*)d_in[2];  // [H, H]
    float* out = (float*)d_out;

    {
        dim3 blk(32, 8);
        dim3 g2(N_IN / 32, HID / 32);
        transpose_win_kernel<<<g2, blk>>>(w_in);
        dim3 g1(HID / 32, HID / 32);
        transpose_wrec_kernel<<<g1, blk>>>(w_rec);
    }

    init_flags_kernel<<<1, 256>>>();

    fused_kernel<<<N_TOTAL_CTAS, 256>>>(x, out);
}

// round 16
// speedup vs baseline: 1.0618x; 1.0034x over previous
#include <cuda_runtime.h>
#include <cstdint>

// Problem constants
#define T_STEPS 512
#define BATCH   64
#define N_IN    512
#define HID     1024

// LSNN parameters
#define DT_TAU_MEM   0.1f
#define DT_TAU_SYN   0.2f
#define DT_TAU_ADAPT 1.25e-6f
#define VTH          1.0f
#define BETA         1.8f

// Fused-kernel geometry (r12 layout: scan bids 0..63, workers 64..295)
#define N_SCAN_CTAS  64
#define N_GEMM_CTAS  232
#define N_TOTAL_CTAS (N_SCAN_CTAS + N_GEMM_CTAS)   // 296 = 148 SMs * 2
#define N_ROWBLK     256                            // (T*B)/128 row-blocks
#define N_COLBLK     8                              // HID/128
#define N_TILES      (N_ROWBLK * N_COLBLK)          // 2048
// Work-stealing split: last 256 tiles (rb >= 224, needed only at t >= 448)
#define R1_TILES     1792
#define R2_TILES     256

// ---------------------------------------------------------------------------
// Scratch
// ---------------------------------------------------------------------------
__device__ float g_curin[(size_t)T_STEPS * BATCH * HID];   // x @ w_in^T, [T,B,H]
__device__ float g_wrecT[(size_t)HID * HID];               // w_rec^T
__device__ float g_winT [(size_t)N_IN * HID];              // w_in^T
__device__ int   g_cnt[N_ROWBLK];                          // col-tiles done per row-block
__device__ int   g_tile;                                   // range-1 queue head
__device__ int   g_t2;                                     // range-2 queue head (shared)

// ---------------------------------------------------------------------------
// Packed fp32x2 helpers
// ---------------------------------------------------------------------------
__device__ __forceinline__ unsigned long long pack_f32x2(float lo, float hi)
{
    unsigned long long r;
    asm("mov.b64 %0, {%1, %2};" : "=l"(r) : "r"(__float_as_uint(lo)), "r"(__float_as_uint(hi)));
    return r;
}
__device__ __forceinline__ void fma_f32x2(unsigned long long& d,
                                          unsigned long long a, unsigned long long b)
{
    asm("fma.rn.f32x2 %0, %1, %2, %0;" : "+l"(d) : "l"(a), "l"(b));
}
__device__ __forceinline__ void add_f32x2(unsigned long long& d, unsigned long long a)
{
    asm("add.rn.f32x2 %0, %0, %1;" : "+l"(d) : "l"(a));
}
__device__ __forceinline__ float2 unpack_f32x2(unsigned long long p)
{
    unsigned int lo, hi;
    asm("mov.b64 {%0, %1}, %2;" : "=r"(lo), "=r"(hi) : "l"(p));
    return make_float2(__uint_as_float(lo), __uint_as_float(hi));
}

// ---------------------------------------------------------------------------
// Tiled transposes
// ---------------------------------------------------------------------------
__device__ __forceinline__ void transpose_impl(const float* __restrict__ in,
                                               float* __restrict__ out,
                                               int rows, int cols)
{
    __shared__ float tile[32][33];
    int c = blockIdx.x * 32 + threadIdx.x;
    int r = blockIdx.y * 32 + threadIdx.y;
#pragma unroll
    for (int j = 0; j < 32; j += 8) {
        if (r + j < rows && c < cols)
            tile[threadIdx.y + j][threadIdx.x] = in[(size_t)(r + j) * cols + c];
    }
    __syncthreads();
    int c2 = blockIdx.y * 32 + threadIdx.x;
    int r2 = blockIdx.x * 32 + threadIdx.y;
#pragma unroll
    for (int j = 0; j < 32; j += 8) {
        if (r2 + j < cols && c2 < rows)
            out[(size_t)(r2 + j) * rows + c2] = tile[threadIdx.x][threadIdx.y + j];
    }
}

__global__ void transpose_wrec_kernel(const float* __restrict__ w_rec)
{
    transpose_impl(w_rec, g_wrecT, HID, HID);
}

__global__ void transpose_win_kernel(const float* __restrict__ w_in)
{
    transpose_impl(w_in, g_winT, HID, N_IN);
}

__global__ void init_flags_kernel()
{
    if (threadIdx.x < N_ROWBLK) g_cnt[threadIdx.x] = 0;
    if (threadIdx.x == 0) { g_tile = 0; g_t2 = 0; }
}

// ---------------------------------------------------------------------------
// Shared-memory layout (scan region disjoint from GEMM staging so a scan CTA
// can execute stolen GEMM tiles without clobbering its spike list)
// ---------------------------------------------------------------------------
#define BM 128
#define BN 128
#define BK 8
#define TM 8
#define TN 8

#define SM_LIST_OFF 0        // scan: 2 x 1024 int  = 8192 B
#define SM_WCNT_OFF 8192     // scan: 8 int
#define SM_CTRL_OFF 8224     // scan: control ints (flag-ready, steal idx)
#define SM_GEMM_OFF 8256     // GEMM As (8192 B) then Bs (8192 B)
#define SM_BS_OFF   16448
#define SM_TILE_OFF 24640    // worker queue broadcast int
#define SMEM_BYTES  24704

// ---------------------------------------------------------------------------
// One GEMM tile (no queue logic). Starts and ends with __syncthreads.
// ---------------------------------------------------------------------------
__device__ __forceinline__ void gemm_tile(unsigned char* s_raw,
                                          const float* __restrict__ A,
                                          int tile)
{
    float (*As)[BK][BM] = reinterpret_cast<float (*)[BK][BM]>(s_raw + SM_GEMM_OFF);
    float (*Bs)[BK][BN] = reinterpret_cast<float (*)[BK][BN]>(s_raw + SM_BS_OFF);

    const int K = N_IN;
    const int N = HID;
    const int tid = threadIdx.x;

    const int arow = tid >> 1;
    const int ak   = (tid & 1) * 4;
    const int brow = tid >> 5;
    const int bcol = (tid & 31) * 4;
    const int tx = (tid & 15) * TN;
    const int ty = (tid >> 4) * TM;

    const int rb = tile >> 3;       // row-block (covers t = 2*rb, 2*rb+1)
    const int cb = tile & 7;
    const int bm = rb * BM;
    const int bn = cb * BN;

    unsigned long long acc2[TM][TN / 2];
#pragma unroll
    for (int m = 0; m < TM; m++)
#pragma unroll
        for (int j = 0; j < TN / 2; j++) acc2[m][j] = 0ull;

    const float* Aptr = A + (size_t)(bm + arow) * K + ak;
    const float* Bptr = g_winT + (size_t)brow * N + bn + bcol;

    float4 av = *(const float4*)Aptr;  Aptr += BK;
    float4 bv = *(const float4*)Bptr;  Bptr += (size_t)BK * N;
    As[0][ak + 0][arow] = av.x;
    As[0][ak + 1][arow] = av.y;
    As[0][ak + 2][arow] = av.z;
    As[0][ak + 3][arow] = av.w;
    *(float4*)&Bs[0][brow][bcol] = bv;
    __syncthreads();

    const int NIT = K / BK;   // 64
    for (int k0 = 0; k0 < NIT; k0++) {
        const int cur = k0 & 1;

        if (k0 + 1 < NIT) {
            av = *(const float4*)Aptr;  Aptr += BK;
            bv = *(const float4*)Bptr;  Bptr += (size_t)BK * N;
        }

#pragma unroll
        for (int kk = 0; kk < BK; kk++) {
            const float4* asp = (const float4*)&As[cur][kk][ty];
            float4 a0 = asp[0];
            float4 a1 = asp[1];
            unsigned long long a2[TM];
            a2[0] = pack_f32x2(a0.x, a0.x);
            a2[1] = pack_f32x2(a0.y, a0.y);
            a2[2] = pack_f32x2(a0.z, a0.z);
            a2[3] = pack_f32x2(a0.w, a0.w);
            a2[4] = pack_f32x2(a1.x, a1.x);
            a2[5] = pack_f32x2(a1.y, a1.y);
            a2[6] = pack_f32x2(a1.z, a1.z);
            a2[7] = pack_f32x2(a1.w, a1.w);

            const ulonglong2* bsp = (const ulonglong2*)&Bs[cur][kk][tx];
            ulonglong2 bq0 = bsp[0];
            ulonglong2 bq1 = bsp[1];
            unsigned long long bb[TN / 2] = {bq0.x, bq0.y, bq1.x, bq1.y};

#pragma unroll
            for (int m = 0; m < TM; m++)
#pragma unroll
                for (int j = 0; j < TN / 2; j++)
                    fma_f32x2(acc2[m][j], a2[m], bb[j]);
        }

        if (k0 + 1 < NIT) {
            const int nxt = cur ^ 1;
            As[nxt][ak + 0][arow] = av.x;
            As[nxt][ak + 1][arow] = av.y;
            As[nxt][ak + 2][arow] = av.z;
            As[nxt][ak + 3][arow] = av.w;
            *(float4*)&Bs[nxt][brow][bcol] = bv;
            __syncthreads();
        }
    }

    float* Cbase = g_curin + (size_t)(bm + ty) * N + bn + tx;
#pragma unroll
    for (int m = 0; m < TM; m++) {
        float* crow = Cbase + (size_t)m * N;
#pragma unroll
        for (int j = 0; j < TN / 2; j += 2) {
            float2 v0 = unpack_f32x2(acc2[m][j]);
            float2 v1 = unpack_f32x2(acc2[m][j + 1]);
            *(float4*)(crow + 2 * j) = make_float4(v0.x, v0.y, v1.x, v1.y);
        }
    }

    __syncthreads();                  // all threads' stores issued
    if (tid == 0) {
        __threadfence();              // make them device-visible
        atomicAdd(&g_cnt[rb], 1);     // publish this col-tile
    }
    __syncthreads();                  // smem reuse safe for next tile
}

// ---------------------------------------------------------------------------
// Worker role: drain range 1, then range 2 (shared with stealers)
// ---------------------------------------------------------------------------
__device__ __forceinline__ void gemm_role(unsigned char* s_raw,
                                          const float* __restrict__ A)
{
    int* s_tile = reinterpret_cast<int*>(s_raw + SM_TILE_OFF);
    const int tid = threadIdx.x;

    for (;;) {
        if (tid == 0) *s_tile = atomicAdd(&g_tile, 1);
        __syncthreads();
        const int tile = *s_tile;
        if (tile >= R1_TILES) break;
        gemm_tile(s_raw, A, tile);
    }
    for (;;) {
        if (tid == 0) *s_tile = atomicAdd(&g_t2, 1);
        __syncthreads();
        const int i2 = *s_tile;
        if (i2 >= R2_TILES) break;
        gemm_tile(s_raw, A, R1_TILES + i2);
    }
}

// ---------------------------------------------------------------------------
// Scan role (r12 structure) + steal-while-waiting
// ---------------------------------------------------------------------------
__device__ __forceinline__ void scan_role(unsigned char* s_raw,
                                          const float* __restrict__ A,
                                          float* __restrict__ out)
{
    int  (*s_list)[HID] = reinterpret_cast<int (*)[HID]>(s_raw + SM_LIST_OFF);
    int*  s_warpcnt     = reinterpret_cast<int*>(s_raw + SM_WCNT_OFF);
    int*  s_ctrl        = reinterpret_cast<int*>(s_raw + SM_CTRL_OFF);

    const int tid   = threadIdx.x;
    const int batch = blockIdx.x;
    const int lane  = tid & 31;
    const int wid   = tid >> 5;
    const int h0    = tid * 4;
    const unsigned FULL = 0xffffffffu;

    float v[4]   = {0.f, 0.f, 0.f, 0.f};
    float cur[4] = {0.f, 0.f, 0.f, 0.f};
    float bth[4] = {VTH, VTH, VTH, VTH};
    float zl[4]  = {0.f, 0.f, 0.f, 0.f};
    int cnt = 0;
    int buf = 0;

    const float* cin  = g_curin + (size_t)batch * HID + h0;
    float*       outp = out     + (size_t)batch * HID + h0;
    const size_t strideT = (size_t)BATCH * HID;

    float4 gin, pgin;

    for (int t = 0; t < T_STEPS; t++) {
        if ((t & 1) == 0) {
            // wait for row-block t/2; steal range-2 GEMM tiles while waiting
            for (;;) {
                if (tid == 0) {
                    int c;
                    asm volatile("ld.acquire.gpu.global.b32 %0, [%1];"
                                 : "=r"(c) : "l"(&g_cnt[t >> 1]) : "memory");
                    s_ctrl[0] = (c >= N_COLBLK) ? 1 : 0;
                }
                __syncthreads();
                if (s_ctrl[0]) break;

                if (tid == 0) s_ctrl[1] = atomicAdd(&g_t2, 1);
                __syncthreads();
                const int i2 = s_ctrl[1];
                if (i2 < R2_TILES) {
                    gemm_tile(s_raw, A, R1_TILES + i2);   // bounded detour
                } else {
                    if (tid == 0) __nanosleep(512);
                    __syncthreads();
                }
            }
            __threadfence();   // order data loads after the flag read
            gin  = *(const float4*)(cin + (size_t)t * strideT);
            pgin = *(const float4*)(cin + (size_t)(t + 1) * strideT);
        } else {
            gin = pgin;
        }

        // recurrent input: sum of w_recT rows over previous step's spikes
        unsigned long long r01 = 0ull, r23 = 0ull;
        {
            const int* lst = s_list[buf];
            const int4* lst4 = (const int4*)lst;
            int k = 0;
            for (; k + 4 <= cnt; k += 4) {
                int4 i4 = lst4[k >> 2];
                ulonglong2 w0 = *(const ulonglong2*)(g_wrecT + (size_t)i4.x * HID + h0);
                ulonglong2 w1 = *(const ulonglong2*)(g_wrecT + (size_t)i4.y * HID + h0);
                ulonglong2 w2 = *(const ulonglong2*)(g_wrecT + (size_t)i4.z * HID + h0);
                ulonglong2 w3 = *(const ulonglong2*)(g_wrecT + (size_t)i4.w * HID + h0);
                add_f32x2(r01, w0.x); add_f32x2(r23, w0.y);
                add_f32x2(r01, w1.x); add_f32x2(r23, w1.y);
                add_f32x2(r01, w2.x); add_f32x2(r23, w2.y);
                add_f32x2(r01, w3.x); add_f32x2(r23, w3.y);
            }
            for (; k < cnt; k++) {
                ulonglong2 w = *(const ulonglong2*)(g_wrecT + (size_t)lst[k] * HID + h0);
                add_f32x2(r01, w.x); add_f32x2(r23, w.y);
            }
        }
        float rec[4];
        {
            float2 a = unpack_f32x2(r01);
            float2 b = unpack_f32x2(r23);
            rec[0] = a.x; rec[1] = a.y; rec[2] = b.x; rec[3] = b.y;
        }
        const float ginv[4] = {gin.x, gin.y, gin.z, gin.w};

        // elementwise dynamics
        bool z[4];
        float zf[4];
#pragma unroll
        for (int j = 0; j < 4; j++) {
            float vd   = v[j] + DT_TAU_MEM * (cur[j] - v[j]);
            float idec = cur[j] - DT_TAU_SYN * cur[j];
            float bd   = bth[j] + DT_TAU_ADAPT * (VTH - bth[j]);
            z[j]  = (vd - bd) > 0.0f;
            zf[j] = z[j] ? 1.0f : 0.0f;
            v[j]   = z[j] ? 0.0f : vd;
            bth[j] = bd + (z[j] ? BETA : 0.0f);
            cur[j] = (idec + ginv[j]) + rec[j];
            zl[j]  = zf[j];
        }

        *(float4*)(outp + (size_t)t * strideT) = make_float4(zf[0], zf[1], zf[2], zf[3]);

        // rebuild spike list (double-buffered, 2 barriers)
        int mycnt = (int)z[0] + (int)z[1] + (int)z[2] + (int)z[3];

        int inc = mycnt;
#pragma unroll
        for (int off = 1; off < 32; off *= 2) {
            int nbr = __shfl_up_sync(FULL, inc, off);
            if (lane >= off) inc += nbr;
        }
        int tex = inc - mycnt;
        if (lane == 31) s_warpcnt[wid] = inc;
        __syncthreads();

        int wc = (lane < 8) ? s_warpcnt[lane] : 0;
        int winc = wc;
#pragma unroll
        for (int off = 1; off < 8; off *= 2) {
            int nbr = __shfl_up_sync(FULL, winc, off);
            if (lane >= off) winc += nbr;
        }
        int total = __shfl_sync(FULL, winc, 7);
        int wbase = __shfl_sync(FULL, winc, wid) - __shfl_sync(FULL, wc, wid);

        const int nbuf = buf ^ 1;
        int p = wbase + tex;
        int* nl = s_list[nbuf];
        if (z[0]) nl[p++] = h0 + 0;
        if (z[1]) nl[p++] = h0 + 1;
        if (z[2]) nl[p++] = h0 + 2;
        if (z[3]) nl[p++] = h0 + 3;

        cnt = total;
        buf = nbuf;
        __syncthreads();
    }

    // final states: (zf, vf, if, bf) appended after outs [T,B,H]
    const size_t BH = (size_t)BATCH * HID;
    float* fbase = out + (size_t)T_STEPS * BH + (size_t)batch * HID + h0;
    *(float4*)(fbase + 0 * BH) = make_float4(zl[0], zl[1], zl[2], zl[3]);
    *(float4*)(fbase + 1 * BH) = make_float4(v[0], v[1], v[2], v[3]);
    *(float4*)(fbase + 2 * BH) = make_float4(cur[0], cur[1], cur[2], cur[3]);
    *(float4*)(fbase + 3 * BH) = make_float4(bth[0], bth[1], bth[2], bth[3]);
}

__global__ void __launch_bounds__(256, 2)
fused_kernel(const float* __restrict__ A, float* __restrict__ out)
{
    __shared__ __align__(16) unsigned char s_raw[SMEM_BYTES];
    if (blockIdx.x < N_SCAN_CTAS) scan_role(s_raw, A, out);
    else                          gemm_role(s_raw, A);
}

// ---------------------------------------------------------------------------
// Launch
// ---------------------------------------------------------------------------
extern "C" void kernel_launch(void* const* d_in, const int* in_sizes, int n_in,
                              void* d_out, int out_size)
{
    const float* x     = (const float*)d_in[0];  // [T, B, N_IN]
    const float* w_in  = (const float*)d_in[1];  // [H, N_IN]
    const float* w_rec = (const float*)d_in[2];  // [H, H]
    float* out = (float*)d_out;

    {
        dim3 blk(32, 8);
        dim3 g2(N_IN / 32, HID / 32);
        transpose_win_kernel<<<g2, blk>>>(w_in);
        dim3 g1(HID / 32, HID / 32);
        transpose_wrec_kernel<<<g1, blk>>>(w_rec);
    }

    init_flags_kernel<<<1, 256>>>();

    fused_kernel<<<N_TOTAL_CTAS, 256>>>(x, out);
}

// round 17
// speedup vs baseline: 1.0877x; 1.0244x over previous
#include <cuda_runtime.h>
#include <cstdint>

// Problem constants
#define T_STEPS 512
#define BATCH   64
#define N_IN    512
#define HID     1024

// LSNN parameters
#define DT_TAU_MEM   0.1f
#define DT_TAU_SYN   0.2f
#define DT_TAU_ADAPT 1.25e-6f
#define VTH          1.0f
#define BETA         1.8f

// Fused-kernel geometry (r12 layout: scan bids 0..63, workers 64..295)
#define N_SCAN_CTAS  64
#define N_GEMM_CTAS  232
#define N_TOTAL_CTAS (N_SCAN_CTAS + N_GEMM_CTAS)   // 296 = 148 SMs * 2
#define N_ROWBLK     256                            // (T*B)/128 row-blocks
#define N_COLBLK     8                              // HID/128
#define N_TILES      (N_ROWBLK * N_COLBLK)          // 2048

// ---------------------------------------------------------------------------
// Scratch
// ---------------------------------------------------------------------------
__device__ float g_curin[(size_t)T_STEPS * BATCH * HID];   // x @ w_in^T, [T,B,H]
__device__ float g_wrecT[(size_t)HID * HID];               // w_rec^T
__device__ float g_winT [(size_t)N_IN * HID];              // w_in^T
__device__ int   g_cnt[N_ROWBLK];                          // col-tiles done per row-block
__device__ int   g_tile;                                   // dynamic tile queue head

// ---------------------------------------------------------------------------
// Packed fp32x2 helpers
// ---------------------------------------------------------------------------
__device__ __forceinline__ unsigned long long pack_f32x2(float lo, float hi)
{
    unsigned long long r;
    asm("mov.b64 %0, {%1, %2};" : "=l"(r) : "r"(__float_as_uint(lo)), "r"(__float_as_uint(hi)));
    return r;
}
__device__ __forceinline__ void fma_f32x2(unsigned long long& d,
                                          unsigned long long a, unsigned long long b)
{
    asm("fma.rn.f32x2 %0, %1, %2, %0;" : "+l"(d) : "l"(a), "l"(b));
}
__device__ __forceinline__ void add_f32x2(unsigned long long& d, unsigned long long a)
{
    asm("add.rn.f32x2 %0, %0, %1;" : "+l"(d) : "l"(a));
}
__device__ __forceinline__ float2 unpack_f32x2(unsigned long long p)
{
    unsigned int lo, hi;
    asm("mov.b64 {%0, %1}, %2;" : "=r"(lo), "=r"(hi) : "l"(p));
    return make_float2(__uint_as_float(lo), __uint_as_float(hi));
}

// ---------------------------------------------------------------------------
// Tiled transposes
// ---------------------------------------------------------------------------
__device__ __forceinline__ void transpose_impl(const float* __restrict__ in,
                                               float* __restrict__ out,
                                               int rows, int cols)
{
    __shared__ float tile[32][33];
    int c = blockIdx.x * 32 + threadIdx.x;
    int r = blockIdx.y * 32 + threadIdx.y;
#pragma unroll
    for (int j = 0; j < 32; j += 8) {
        if (r + j < rows && c < cols)
            tile[threadIdx.y + j][threadIdx.x] = in[(size_t)(r + j) * cols + c];
    }
    __syncthreads();
    int c2 = blockIdx.y * 32 + threadIdx.x;
    int r2 = blockIdx.x * 32 + threadIdx.y;
#pragma unroll
    for (int j = 0; j < 32; j += 8) {
        if (r2 + j < cols && c2 < rows)
            out[(size_t)(r2 + j) * rows + c2] = tile[threadIdx.x][threadIdx.y + j];
    }
}

__global__ void transpose_wrec_kernel(const float* __restrict__ w_rec)
{
    transpose_impl(w_rec, g_wrecT, HID, HID);
}

__global__ void transpose_win_kernel(const float* __restrict__ w_in)
{
    transpose_impl(w_in, g_winT, HID, N_IN);
}

__global__ void init_flags_kernel()
{
    if (threadIdx.x < N_ROWBLK) g_cnt[threadIdx.x] = 0;
    if (threadIdx.x == 0) g_tile = 0;
}

// ---------------------------------------------------------------------------
// Fused kernel: 296 CTAs of 256 threads.
//   bid <  64 : LSNN scan (one CTA per batch), waits on g_cnt row-block flags
//   bid >= 64 : GEMM worker pulling tiles from a dynamic t-ordered queue
// ---------------------------------------------------------------------------
#define BM 128
#define BN 128
#define BK 8
#define TM 8
#define TN 8
#define SMEM_BYTES 16896

__device__ __forceinline__ void gemm_role(unsigned char* s_raw,
                                          const float* __restrict__ A)
{
    float (*As)[BK][BM] = reinterpret_cast<float (*)[BK][BM]>(s_raw);
    float (*Bs)[BK][BN] = reinterpret_cast<float (*)[BK][BN]>(s_raw + 8192);
    int* s_tile = reinterpret_cast<int*>(s_raw + 16384);

    const int K = N_IN;
    const int N = HID;
    const int tid = threadIdx.x;
    const int lane = tid & 31;
    const int wrp  = tid >> 5;

    const int arow = tid >> 1;
    const int ak   = (tid & 1) * 4;
    const int brow = tid >> 5;
    const int bcol = (tid & 31) * 4;

    // Warp covers 8 tx x 4 ty (halves unique smem bytes per warp per kk
    // vs the old 16 tx x 2 ty map; per-thread work identical).
    const int tx = (((wrp & 1) << 3) + (lane & 7)) * TN;
    const int ty = ((((wrp >> 1) & 3) << 2) + (lane >> 3)) * TM;

    for (;;) {
        // grab next tile in t-major order (dynamic balance, minimal tail)
        if (tid == 0) *s_tile = atomicAdd(&g_tile, 1);
        __syncthreads();
        const int tile = *s_tile;
        __syncthreads();
        if (tile >= N_TILES) break;

        const int rb = tile >> 3;       // row-block (covers t = 2*rb, 2*rb+1)
        const int cb = tile & 7;
        const int bm = rb * BM;
        const int bn = cb * BN;

        unsigned long long acc2[TM][TN / 2];
#pragma unroll
        for (int m = 0; m < TM; m++)
#pragma unroll
            for (int j = 0; j < TN / 2; j++) acc2[m][j] = 0ull;

        const float* Aptr = A + (size_t)(bm + arow) * K + ak;
        const float* Bptr = g_winT + (size_t)brow * N + bn + bcol;

        float4 av = *(const float4*)Aptr;  Aptr += BK;
        float4 bv = *(const float4*)Bptr;  Bptr += (size_t)BK * N;
        As[0][ak + 0][arow] = av.x;
        As[0][ak + 1][arow] = av.y;
        As[0][ak + 2][arow] = av.z;
        As[0][ak + 3][arow] = av.w;
        *(float4*)&Bs[0][brow][bcol] = bv;
        __syncthreads();

        const int NIT = K / BK;   // 64
        for (int k0 = 0; k0 < NIT; k0++) {
            const int cur = k0 & 1;

            if (k0 + 1 < NIT) {
                av = *(const float4*)Aptr;  Aptr += BK;
                bv = *(const float4*)Bptr;  Bptr += (size_t)BK * N;
            }

#pragma unroll
            for (int kk = 0; kk < BK; kk++) {
                const float4* asp = (const float4*)&As[cur][kk][ty];
                float4 a0 = asp[0];
                float4 a1 = asp[1];
                unsigned long long a2[TM];
                a2[0] = pack_f32x2(a0.x, a0.x);
                a2[1] = pack_f32x2(a0.y, a0.y);
                a2[2] = pack_f32x2(a0.z, a0.z);
                a2[3] = pack_f32x2(a0.w, a0.w);
                a2[4] = pack_f32x2(a1.x, a1.x);
                a2[5] = pack_f32x2(a1.y, a1.y);
                a2[6] = pack_f32x2(a1.z, a1.z);
                a2[7] = pack_f32x2(a1.w, a1.w);

                const ulonglong2* bsp = (const ulonglong2*)&Bs[cur][kk][tx];
                ulonglong2 bq0 = bsp[0];
                ulonglong2 bq1 = bsp[1];
                unsigned long long bb[TN / 2] = {bq0.x, bq0.y, bq1.x, bq1.y};

#pragma unroll
                for (int m = 0; m < TM; m++)
#pragma unroll
                    for (int j = 0; j < TN / 2; j++)
                        fma_f32x2(acc2[m][j], a2[m], bb[j]);
            }

            if (k0 + 1 < NIT) {
                const int nxt = cur ^ 1;
                As[nxt][ak + 0][arow] = av.x;
                As[nxt][ak + 1][arow] = av.y;
                As[nxt][ak + 2][arow] = av.z;
                As[nxt][ak + 3][arow] = av.w;
                *(float4*)&Bs[nxt][brow][bcol] = bv;
                __syncthreads();
            }
        }

        float* Cbase = g_curin + (size_t)(bm + ty) * N + bn + tx;
#pragma unroll
        for (int m = 0; m < TM; m++) {
            float* crow = Cbase + (size_t)m * N;
#pragma unroll
            for (int j = 0; j < TN / 2; j += 2) {
                float2 v0 = unpack_f32x2(acc2[m][j]);
                float2 v1 = unpack_f32x2(acc2[m][j + 1]);
                *(float4*)(crow + 2 * j) = make_float4(v0.x, v0.y, v1.x, v1.y);
            }
        }

        __syncthreads();                  // all threads' stores issued
        if (tid == 0) {
            __threadfence();              // make them device-visible
            atomicAdd(&g_cnt[rb], 1);     // publish this col-tile
        }
        __syncthreads();                  // keep smem reuse safe for next tile
    }
}

__device__ __forceinline__ void scan_role(unsigned char* s_raw,
                                          float* __restrict__ out)
{
    int  (*s_list)[HID] = reinterpret_cast<int (*)[HID]>(s_raw);       // 2 x 1024 ints
    int*  s_warpcnt     = reinterpret_cast<int*>(s_raw + 8192);        // 8 ints

    const int tid   = threadIdx.x;
    const int batch = blockIdx.x;
    const int lane  = tid & 31;
    const int wid   = tid >> 5;
    const int h0    = tid * 4;
    const unsigned FULL = 0xffffffffu;

    float v[4]   = {0.f, 0.f, 0.f, 0.f};
    float cur[4] = {0.f, 0.f, 0.f, 0.f};
    float bth[4] = {VTH, VTH, VTH, VTH};
    float zl[4]  = {0.f, 0.f, 0.f, 0.f};
    int cnt = 0;
    int buf = 0;

    const float* cin  = g_curin + (size_t)batch * HID + h0;
    float*       outp = out     + (size_t)batch * HID + h0;
    const size_t strideT = (size_t)BATCH * HID;

    float4 gin, pgin;

    for (int t = 0; t < T_STEPS; t++) {
        if ((t & 1) == 0) {
            // wait for row-block t/2 (covers steps t and t+1, all batches)
            if (tid == 0) {
                int* flag = &g_cnt[t >> 1];
                int c;
                for (;;) {
                    asm volatile("ld.acquire.gpu.global.b32 %0, [%1];"
                                 : "=r"(c) : "l"(flag) : "memory");
                    if (c >= N_COLBLK) break;
                    __nanosleep(256);
                }
            }
            __syncthreads();
            __threadfence();   // order subsequent data loads after the flag read
            gin  = *(const float4*)(cin + (size_t)t * strideT);
            pgin = *(const float4*)(cin + (size_t)(t + 1) * strideT);
        } else {
            gin = pgin;
        }

        // recurrent input: sum of w_recT rows over previous step's spikes
        unsigned long long r01 = 0ull, r23 = 0ull;
        {
            const int* lst = s_list[buf];
            const int4* lst4 = (const int4*)lst;
            int k = 0;
            for (; k + 4 <= cnt; k += 4) {
                int4 i4 = lst4[k >> 2];
                ulonglong2 w0 = *(const ulonglong2*)(g_wrecT + (size_t)i4.x * HID + h0);
                ulonglong2 w1 = *(const ulonglong2*)(g_wrecT + (size_t)i4.y * HID + h0);
                ulonglong2 w2 = *(const ulonglong2*)(g_wrecT + (size_t)i4.z * HID + h0);
                ulonglong2 w3 = *(const ulonglong2*)(g_wrecT + (size_t)i4.w * HID + h0);
                add_f32x2(r01, w0.x); add_f32x2(r23, w0.y);
                add_f32x2(r01, w1.x); add_f32x2(r23, w1.y);
                add_f32x2(r01, w2.x); add_f32x2(r23, w2.y);
                add_f32x2(r01, w3.x); add_f32x2(r23, w3.y);
            }
            for (; k < cnt; k++) {
                ulonglong2 w = *(const ulonglong2*)(g_wrecT + (size_t)lst[k] * HID + h0);
                add_f32x2(r01, w.x); add_f32x2(r23, w.y);
            }
        }
        float rec[4];
        {
            float2 a = unpack_f32x2(r01);
            float2 b = unpack_f32x2(r23);
            rec[0] = a.x; rec[1] = a.y; rec[2] = b.x; rec[3] = b.y;
        }
        const float ginv[4] = {gin.x, gin.y, gin.z, gin.w};

        // elementwise dynamics
        bool z[4];
        float zf[4];
#pragma unroll
        for (int j = 0; j < 4; j++) {
            float vd   = v[j] + DT_TAU_MEM * (cur[j] - v[j]);
            float idec = cur[j] - DT_TAU_SYN * cur[j];
            float bd   = bth[j] + DT_TAU_ADAPT * (VTH - bth[j]);
            z[j]  = (vd - bd) > 0.0f;
            zf[j] = z[j] ? 1.0f : 0.0f;
            v[j]   = z[j] ? 0.0f : vd;
            bth[j] = bd + (z[j] ? BETA : 0.0f);
            cur[j] = (idec + ginv[j]) + rec[j];
            zl[j]  = zf[j];
        }

        *(float4*)(outp + (size_t)t * strideT) = make_float4(zf[0], zf[1], zf[2], zf[3]);

        // rebuild spike list (double-buffered, 2 barriers)
        int mycnt = (int)z[0] + (int)z[1] + (int)z[2] + (int)z[3];

        int inc = mycnt;
#pragma unroll
        for (int off = 1; off < 32; off *= 2) {
            int nbr = __shfl_up_sync(FULL, inc, off);
            if (lane >= off) inc += nbr;
        }
        int tex = inc - mycnt;
        if (lane == 31) s_warpcnt[wid] = inc;
        __syncthreads();

        int wc = (lane < 8) ? s_warpcnt[lane] : 0;
        int winc = wc;
#pragma unroll
        for (int off = 1; off < 8; off *= 2) {
            int nbr = __shfl_up_sync(FULL, winc, off);
            if (lane >= off) winc += nbr;
        }
        int total = __shfl_sync(FULL, winc, 7);
        int wbase = __shfl_sync(FULL, winc, wid) - __shfl_sync(FULL, wc, wid);

        const int nbuf = buf ^ 1;
        int p = wbase + tex;
        int* nl = s_list[nbuf];
        if (z[0]) nl[p++] = h0 + 0;
        if (z[1]) nl[p++] = h0 + 1;
        if (z[2]) nl[p++] = h0 + 2;
        if (z[3]) nl[p++] = h0 + 3;

        cnt = total;
        buf = nbuf;
        __syncthreads();
    }

    // final states: (zf, vf, if, bf) appended after outs [T,B,H]
    const size_t BH = (size_t)BATCH * HID;
    float* fbase = out + (size_t)T_STEPS * BH + (size_t)batch * HID + h0;
    *(float4*)(fbase + 0 * BH) = make_float4(zl[0], zl[1], zl[2], zl[3]);
    *(float4*)(fbase + 1 * BH) = make_float4(v[0], v[1], v[2], v[3]);
    *(float4*)(fbase + 2 * BH) = make_float4(cur[0], cur[1], cur[2], cur[3]);
    *(float4*)(fbase + 3 * BH) = make_float4(bth[0], bth[1], bth[2], bth[3]);
}

__global__ void __launch_bounds__(256, 2)
fused_kernel(const float* __restrict__ A, float* __restrict__ out)
{
    __shared__ __align__(16) unsigned char s_raw[SMEM_BYTES];
    if (blockIdx.x < N_SCAN_CTAS) scan_role(s_raw, out);
    else                          gemm_role(s_raw, A);
}

// ---------------------------------------------------------------------------
// Launch
// ---------------------------------------------------------------------------
extern "C" void kernel_launch(void* const* d_in, const int* in_sizes, int n_in,
                              void* d_out, int out_size)
{
    const float* x     = (const float*)d_in[0];  // [T, B, N_IN]
    const float* w_in  = (const float*)d_in[1];  // [H, N_IN]
    const float* w_rec = (const float*)d_in[2];  // [H, H]
    float* out = (float*)d_out;

    {
        dim3 blk(32, 8);
        dim3 g2(N_IN / 32, HID / 32);
        transpose_win_kernel<<<g2, blk>>>(w_in);
        dim3 g1(HID / 32, HID / 32);
        transpose_wrec_kernel<<<g1, blk>>>(w_rec);
    }

    init_flags_kernel<<<1, 256>>>();

    fused_kernel<<<N_TOTAL_CTAS, 256>>>(x, out);
}